// round 1
// baseline (speedup 1.0000x reference)
#include <cuda_runtime.h>
#include <cuda_bf16.h>
#include <cstdint>

// Problem constants
#define Bb 4
#define Ss 2048
#define Ee 2048
#define Hh 16
#define Dd 128
#define Mm (Bb * Ss)          // 8192
#define N_QKV (3 * Ee)        // 6144
#define HEAD_ELEMS ((size_t)Bb * Hh * Ss * Dd)   // 16,777,216

// Scratch (device globals; no allocation allowed)
__device__ float g_q[(size_t)Bb * Hh * Ss * Dd];   // 64 MB, q after rotary (B,H,S,D)
__device__ float g_y[(size_t)Bb * Ss * Ee];        // 64 MB, attention output (B,S,E)

// ---------------------------------------------------------------------------
// SGEMM 128x128x8, 256 threads, 8x8 per thread.
// MODE 0: C = A*B + bias, row-major write to out0 (proj GEMM)
// MODE 1: QKV epilogue — bias, RoPE on q/k, scatter to (B,H,S,D) layouts
// ---------------------------------------------------------------------------
template <int MODE>
__global__ void __launch_bounds__(256)
mha_sgemm(const float* __restrict__ A, const float* __restrict__ Bw,
          const float* __restrict__ bias,
          const float* __restrict__ cosT, const float* __restrict__ sinT,
          float* __restrict__ out0, float* __restrict__ out1, float* __restrict__ out2,
          int K, int N)
{
    __shared__ float As[8][132];   // padded to kill store conflicts
    __shared__ float Bs[8][128];

    const int t  = threadIdx.x;
    const int tx = t & 15;
    const int ty = t >> 4;
    const int bm = blockIdx.y;
    const int bn = blockIdx.x;
    const int m0 = bm * 128;
    const int n0 = bn * 128;

    float acc[8][8];
#pragma unroll
    for (int i = 0; i < 8; i++)
#pragma unroll
        for (int j = 0; j < 8; j++) acc[i][j] = 0.f;

    const int arow = t >> 1;
    const int acol = (t & 1) * 4;
    const int brow = t >> 5;
    const int bcol = (t & 31) * 4;

    const float* Aptr = A + (size_t)(m0 + arow) * K + acol;
    const float* Bptr = Bw + (size_t)brow * N + n0 + bcol;

    for (int k0 = 0; k0 < K; k0 += 8) {
        float4 av = *(const float4*)(Aptr + k0);
        float4 bv = *(const float4*)(Bptr + (size_t)k0 * N);
        As[acol + 0][arow] = av.x;
        As[acol + 1][arow] = av.y;
        As[acol + 2][arow] = av.z;
        As[acol + 3][arow] = av.w;
        *(float4*)&Bs[brow][bcol] = bv;
        __syncthreads();
#pragma unroll
        for (int kk = 0; kk < 8; kk++) {
            float a[8], b[8];
            *(float4*)(a)     = *(const float4*)&As[kk][ty * 8];
            *(float4*)(a + 4) = *(const float4*)&As[kk][ty * 8 + 4];
            *(float4*)(b)     = *(const float4*)&Bs[kk][tx * 8];
            *(float4*)(b + 4) = *(const float4*)&Bs[kk][tx * 8 + 4];
#pragma unroll
            for (int i = 0; i < 8; i++)
#pragma unroll
                for (int j = 0; j < 8; j++) acc[i][j] += a[i] * b[j];
        }
        __syncthreads();
    }

    // Epilogue
    if (MODE == 0) {
#pragma unroll
        for (int i = 0; i < 8; i++) {
            const int gm = m0 + ty * 8 + i;
            float v[8];
#pragma unroll
            for (int j = 0; j < 8; j++) v[j] = acc[i][j] + bias[n0 + tx * 8 + j];
            size_t idx = (size_t)gm * N + n0 + tx * 8;
            *(float4*)&out0[idx]     = make_float4(v[0], v[1], v[2], v[3]);
            *(float4*)&out0[idx + 4] = make_float4(v[4], v[5], v[6], v[7]);
        }
    } else {
        const int part = n0 >> 11;            // 0=q, 1=k, 2=v
        const int hh   = (n0 & 2047) >> 7;    // head
        const int d0   = tx * 8;              // dim within head (tile is one head)
        float* dst = (part == 0) ? out0 : ((part == 1) ? out1 : out2);
#pragma unroll
        for (int i = 0; i < 8; i++) {
            const int gm = m0 + ty * 8 + i;
            const int bb = gm >> 11;
            const int s  = gm & 2047;
            float v[8];
#pragma unroll
            for (int j = 0; j < 8; j++) v[j] = acc[i][j] + bias[n0 + d0 + j];
            if (part < 2) {
#pragma unroll
                for (int j = 0; j < 8; j += 2) {
                    const int d = d0 + j;
                    const float c0 = cosT[s * Dd + d];
                    const float s0 = sinT[s * Dd + d];
                    const float c1 = cosT[s * Dd + d + 1];
                    const float s1 = sinT[s * Dd + d + 1];
                    const float e = v[j], o = v[j + 1];
                    v[j]     = e * c0 - o * s0;
                    v[j + 1] = o * c1 + e * s1;
                }
            }
            size_t idx = ((((size_t)bb * Hh + hh) * Ss) + s) * Dd + d0;
            *(float4*)&dst[idx]     = make_float4(v[0], v[1], v[2], v[3]);
            *(float4*)&dst[idx + 4] = make_float4(v[4], v[5], v[6], v[7]);
        }
    }
}

// ---------------------------------------------------------------------------
// Flash attention fp32: one block = 64 query rows of one (b, h).
// 256 threads. Q/K transposed in smem with XOR swizzle for conflict-free reads.
// ---------------------------------------------------------------------------
__global__ void __launch_bounds__(256)
mha_attn(const float* __restrict__ qin, const float* __restrict__ kin,
         const float* __restrict__ vin, float* __restrict__ yout)
{
    extern __shared__ float sm[];
    float* Qt  = sm;                 // [128][64] transposed, swizzled
    float* Kt  = Qt + 128 * 64;      // [128][64]
    float* Vs  = Kt + 128 * 64;      // [64][128]
    float* Sp  = Vs + 64 * 128;      // [64][68]
    float* m_s = Sp + 64 * 68;       // [64]
    float* l_s = m_s + 64;           // [64]
    float* a_s = l_s + 64;           // [64] alpha
    float* r_s = a_s + 64;           // [64] row sums

    const int t  = threadIdx.x;
    const int tx = t & 15;
    const int ty = t >> 4;
    const int q0 = blockIdx.x * 64;
    const int h  = blockIdx.y;
    const int b  = blockIdx.z;
    const float scale = 0.08838834764831845f;   // 1/sqrt(128)

    const size_t base = ((size_t)b * Hh + h) * Ss * Dd;
    const float* Q  = qin + base;
    const float* Kg = kin + base;
    const float* Vg = vin + base;

    // Load Q tile transposed+swizzled: Qt[d][i ^ (4*((d>>2)&15))]
    for (int x = t; x < 64 * 32; x += 256) {
        const int i  = x >> 5;
        const int d4 = x & 31;
        float4 v = *(const float4*)(Q + (size_t)(q0 + i) * Dd + d4 * 4);
        const int sw = 4 * (d4 & 15);
        const int ii = i ^ sw;
        Qt[(d4 * 4 + 0) * 64 + ii] = v.x;
        Qt[(d4 * 4 + 1) * 64 + ii] = v.y;
        Qt[(d4 * 4 + 2) * 64 + ii] = v.z;
        Qt[(d4 * 4 + 3) * 64 + ii] = v.w;
    }
    if (t < 64) { m_s[t] = -1e30f; l_s[t] = 0.f; }

    float acc[4][8];
#pragma unroll
    for (int i = 0; i < 4; i++)
#pragma unroll
        for (int j = 0; j < 8; j++) acc[i][j] = 0.f;

    const int qi = ty * 4;
    const int kj = tx * 4;

    for (int kt = 0; kt < Ss; kt += 64) {
        __syncthreads();   // previous tile's Sp/Vs consumers done; Qt ready (1st iter)
        // Load K (transposed+swizzled) and V tiles
        for (int x = t; x < 64 * 32; x += 256) {
            const int j  = x >> 5;
            const int d4 = x & 31;
            float4 kv = *(const float4*)(Kg + (size_t)(kt + j) * Dd + d4 * 4);
            const int sw = 4 * (d4 & 15);
            const int jj = j ^ sw;
            Kt[(d4 * 4 + 0) * 64 + jj] = kv.x;
            Kt[(d4 * 4 + 1) * 64 + jj] = kv.y;
            Kt[(d4 * 4 + 2) * 64 + jj] = kv.z;
            Kt[(d4 * 4 + 3) * 64 + jj] = kv.w;
            float4 vv = *(const float4*)(Vg + (size_t)(kt + j) * Dd + d4 * 4);
            *(float4*)&Vs[j * 128 + d4 * 4] = vv;
        }
        __syncthreads();

        // Scores: sc[i][j] = sum_d Q[qi+i][d] * K[kj+j][d]
        float sc[4][4];
#pragma unroll
        for (int i = 0; i < 4; i++)
#pragma unroll
            for (int j = 0; j < 4; j++) sc[i][j] = 0.f;

        for (int d4 = 0; d4 < 32; d4++) {
            const int sw = 4 * (d4 & 15);
            const int qoff = qi ^ sw;
            const int koff = kj ^ sw;
#pragma unroll
            for (int c = 0; c < 4; c++) {
                const int d = d4 * 4 + c;
                float4 qv = *(const float4*)&Qt[d * 64 + qoff];
                float4 kv = *(const float4*)&Kt[d * 64 + koff];
                const float* qa = (const float*)&qv;
                const float* ka = (const float*)&kv;
#pragma unroll
                for (int i = 0; i < 4; i++)
#pragma unroll
                    for (int j = 0; j < 4; j++) sc[i][j] += qa[i] * ka[j];
            }
        }

        // Raw scores to smem for row-max
#pragma unroll
        for (int i = 0; i < 4; i++)
            *(float4*)&Sp[(qi + i) * 68 + kj] = make_float4(sc[i][0], sc[i][1], sc[i][2], sc[i][3]);
        __syncthreads();

        if (t < 64) {
            float mo = m_s[t];
            float mn = mo;
            for (int j = 0; j < 64; j++) mn = fmaxf(mn, Sp[t * 68 + j] * scale);
            m_s[t] = mn;
            a_s[t] = __expf(mo - mn);
        }
        __syncthreads();

        // P = exp(s*scale - m), partial row sums, write P back
#pragma unroll
        for (int i = 0; i < 4; i++) {
            const int row = qi + i;
            const float mrow = m_s[row];
            float rs = 0.f;
#pragma unroll
            for (int j = 0; j < 4; j++) {
                float p = __expf(sc[i][j] * scale - mrow);
                Sp[row * 68 + kj + j] = p;
                rs += p;
            }
            rs += __shfl_xor_sync(0xffffffffu, rs, 1);
            rs += __shfl_xor_sync(0xffffffffu, rs, 2);
            rs += __shfl_xor_sync(0xffffffffu, rs, 4);
            rs += __shfl_xor_sync(0xffffffffu, rs, 8);
            if (tx == 0) r_s[row] = rs;
        }
        __syncthreads();
        if (t < 64) l_s[t] = l_s[t] * a_s[t] + r_s[t];

        // Rescale accumulator and add P @ V
#pragma unroll
        for (int i = 0; i < 4; i++) {
            const float al = a_s[qi + i];
#pragma unroll
            for (int j = 0; j < 8; j++) acc[i][j] *= al;
        }
        for (int kk = 0; kk < 64; kk++) {
            float4 v1 = *(const float4*)&Vs[kk * 128 + tx * 8];
            float4 v2 = *(const float4*)&Vs[kk * 128 + tx * 8 + 4];
#pragma unroll
            for (int i = 0; i < 4; i++) {
                const float p = Sp[(qi + i) * 68 + kk];
                acc[i][0] += p * v1.x; acc[i][1] += p * v1.y;
                acc[i][2] += p * v1.z; acc[i][3] += p * v1.w;
                acc[i][4] += p * v2.x; acc[i][5] += p * v2.y;
                acc[i][6] += p * v2.z; acc[i][7] += p * v2.w;
            }
        }
    }

    __syncthreads();   // final l_s visible
#pragma unroll
    for (int i = 0; i < 4; i++) {
        const float inv = 1.f / l_s[qi + i];
        const int s_g = q0 + qi + i;
        size_t idx = (((size_t)b * Ss + s_g) * Ee) + h * Dd + tx * 8;
        *(float4*)&yout[idx] = make_float4(acc[i][0] * inv, acc[i][1] * inv,
                                           acc[i][2] * inv, acc[i][3] * inv);
        *(float4*)&yout[idx + 4] = make_float4(acc[i][4] * inv, acc[i][5] * inv,
                                               acc[i][6] * inv, acc[i][7] * inv);
    }
}

// ---------------------------------------------------------------------------
extern "C" void kernel_launch(void* const* d_in, const int* in_sizes, int n_in,
                              void* d_out, int out_size)
{
    const float* x     = (const float*)d_in[0];
    const float* cosT  = (const float*)d_in[1];
    const float* sinT  = (const float*)d_in[2];
    const float* Wqkv  = (const float*)d_in[3];
    const float* bqkv  = (const float*)d_in[4];
    const float* Wproj = (const float*)d_in[5];
    const float* bproj = (const float*)d_in[6];

    float* out  = (float*)d_out;                 // (B,S,E)
    float* kout = out + HEAD_ELEMS;              // (B,H,S,D)
    float* vout = out + 2 * HEAD_ELEMS;          // (B,H,S,D)

    float *qs = nullptr, *ys = nullptr;
    cudaGetSymbolAddress((void**)&qs, g_q);
    cudaGetSymbolAddress((void**)&ys, g_y);

    // 1) QKV GEMM + bias + RoPE + head scatter (k, v land directly in outputs)
    {
        dim3 grid(N_QKV / 128, Mm / 128);
        mha_sgemm<1><<<grid, 256>>>(x, Wqkv, bqkv, cosT, sinT, qs, kout, vout,
                                    Ee, N_QKV);
    }

    // 2) Flash attention
    {
        const int smem = (128 * 64 * 2 + 64 * 128 + 64 * 68 + 4 * 64) * 4;  // 116736 B
        cudaFuncSetAttribute(mha_attn, cudaFuncAttributeMaxDynamicSharedMemorySize, smem);
        dim3 grid(Ss / 64, Hh, Bb);
        mha_attn<<<grid, 256, smem>>>(qs, kout, vout, ys);
    }

    // 3) Projection GEMM
    {
        dim3 grid(Ee / 128, Mm / 128);
        mha_sgemm<0><<<grid, 256>>>(ys, Wproj, bproj, nullptr, nullptr, out,
                                    nullptr, nullptr, Ee, Ee);
    }
}